// round 1
// baseline (speedup 1.0000x reference)
#include <cuda_runtime.h>
#include <math.h>

#define NB 32
#define NL 512
#define NH 8
#define NE 64
#define NS 512

constexpr int ROWS     = 32;    // query rows per block
constexpr int NTHREADS = 256;   // 8 warps, 4 rows each
constexpr int KST      = 130;   // padded stride for transposed K tile [e][s] (even, for float2 align)

constexpr size_t V_SIZE   = (size_t)NB * NL * NH * NE;   // 8388608
constexpr size_t SER_SIZE = (size_t)NB * NH * NL * NS;   // 67108864

// dynamic smem (floats): Qs 2048 | U 16384 (Ks during scores / Ps after) | Vs 8192
constexpr int SMEM_FLOATS = 2048 + 16384 + 8192;         // 26624 floats = 106496 B

__device__ __forceinline__ float2 ffma2(float2 a, float2 b, float2 c) {
    unsigned long long ua = *reinterpret_cast<unsigned long long*>(&a);
    unsigned long long ub = *reinterpret_cast<unsigned long long*>(&b);
    unsigned long long uc = *reinterpret_cast<unsigned long long*>(&c);
    unsigned long long ud;
    asm("fma.rn.f32x2 %0, %1, %2, %3;" : "=l"(ud) : "l"(ua), "l"(ub), "l"(uc));
    return *reinterpret_cast<float2*>(&ud);
}

__global__ void __launch_bounds__(NTHREADS, 2)
anomaly_kernel(const float* __restrict__ Q,
               const float* __restrict__ K,
               const float* __restrict__ V,
               const float* __restrict__ SG,
               float* __restrict__ out)
{
    extern __shared__ float smem[];
    float* Qs = smem;                    // [32][64]
    float* Ks = smem + 2048;             // [64][KST]  (score phase)
    float* Ps = smem + 2048;             // [32][512]  (after score phase; same region)
    float* Vs = smem + 2048 + 16384;     // [128][64]

    const int tile = blockIdx.x & 15;
    const int bh   = blockIdx.x >> 4;
    const int h    = bh & 7;
    const int b    = bh >> 3;
    const int l0   = tile * ROWS;

    const int tid  = threadIdx.x;
    const int lane = tid & 31;
    const int warp = tid >> 5;
    const int r0   = warp * 4;

    // element (b,l,h,e) lives at ((b*NL + l)*NH + h)*NE + e ; row stride NH*NE = 512
    const float* qbase = Q + ((size_t)(b * NL + l0) * NH + h) * NE;
    const float* kcol  = K + ((size_t)(b * NL) * NH + h) * NE;
    const float* vcol  = V + ((size_t)(b * NL) * NH + h) * NE;

    // ---- load Q block (32 x 64) ----
    {
        const int e  = tid & 63;
        const int rr = tid >> 6;
        #pragma unroll
        for (int i = 0; i < 8; i++) {
            int r = rr + i * 4;
            Qs[r * 64 + e] = qbase[(size_t)r * (NH * NE) + e];
        }
    }

    // ---- scores: acc[r][p] covers s = p*64 + 2*lane + {0,1} ----
    float2 acc[4][8];
    #pragma unroll
    for (int r = 0; r < 4; r++)
        #pragma unroll
        for (int p = 0; p < 8; p++) acc[r][p] = make_float2(0.f, 0.f);

    for (int c = 0; c < 4; c++) {
        __syncthreads();  // also makes Qs visible on first iter; protects Ks reuse after
        {   // load K chunk [c*128, c*128+128) transposed into Ks[e][s]
            const int e  = tid & 63;
            const int ss = tid >> 6;
            const float* kc = kcol + (size_t)(c * 128) * (NH * NE);
            #pragma unroll
            for (int i = 0; i < 32; i++) {
                int s = ss + i * 4;
                Ks[e * KST + s] = kc[(size_t)s * (NH * NE) + e];
            }
        }
        __syncthreads();
        const int sA = 2 * lane;
        const int sB = 64 + 2 * lane;
        #pragma unroll
        for (int e = 0; e < 64; e += 2) {
            float2 kA0 = *(const float2*)&Ks[e * KST + sA];
            float2 kB0 = *(const float2*)&Ks[e * KST + sB];
            float2 kA1 = *(const float2*)&Ks[(e + 1) * KST + sA];
            float2 kB1 = *(const float2*)&Ks[(e + 1) * KST + sB];
            #pragma unroll
            for (int r = 0; r < 4; r++) {
                float2 qq = *(const float2*)&Qs[(r0 + r) * 64 + e];
                float2 q0 = make_float2(qq.x, qq.x);
                float2 q1 = make_float2(qq.y, qq.y);
                acc[r][2 * c]     = ffma2(q0, kA0, acc[r][2 * c]);
                acc[r][2 * c + 1] = ffma2(q0, kB0, acc[r][2 * c + 1]);
                acc[r][2 * c]     = ffma2(q1, kA1, acc[r][2 * c]);
                acc[r][2 * c + 1] = ffma2(q1, kB1, acc[r][2 * c + 1]);
            }
        }
    }
    __syncthreads();  // all warps done reading Ks; region becomes Ps

    // ---- softmax (rows r0..r0+3, each warp owns its rows fully) ----
    const float scale = 0.125f;  // 1/sqrt(64)
    #pragma unroll
    for (int r = 0; r < 4; r++) {
        float m = -3.0e38f;
        #pragma unroll
        for (int p = 0; p < 8; p++) {
            acc[r][p].x *= scale;
            acc[r][p].y *= scale;
            m = fmaxf(m, fmaxf(acc[r][p].x, acc[r][p].y));
        }
        #pragma unroll
        for (int o = 16; o > 0; o >>= 1)
            m = fmaxf(m, __shfl_xor_sync(0xffffffffu, m, o));
        float sum = 0.f;
        #pragma unroll
        for (int p = 0; p < 8; p++) {
            acc[r][p].x = __expf(acc[r][p].x - m);
            acc[r][p].y = __expf(acc[r][p].y - m);
            sum += acc[r][p].x + acc[r][p].y;
        }
        #pragma unroll
        for (int o = 16; o > 0; o >>= 1)
            sum += __shfl_xor_sync(0xffffffffu, sum, o);
        float inv = 1.0f / sum;
        #pragma unroll
        for (int p = 0; p < 8; p++) {
            acc[r][p].x *= inv;
            acc[r][p].y *= inv;
        }
    }

    // ---- write series to gmem + stage into Ps ----
    float* serout = out + V_SIZE + (((size_t)b * NH + h) * NL + l0) * NS;
    #pragma unroll
    for (int r = 0; r < 4; r++) {
        float* sp = serout + (size_t)(r0 + r) * NS;
        #pragma unroll
        for (int p = 0; p < 8; p++) {
            int s = p * 64 + 2 * lane;
            *(float2*)&Ps[(r0 + r) * 512 + s] = acc[r][p];
            *(float2*)&sp[s] = acc[r][p];
        }
    }

    // ---- prior (independent of scores) ----
    {
        const float c0 = 0.3989422804014327f;  // 1/sqrt(2*pi)
        #pragma unroll
        for (int r = 0; r < 4; r++) {
            const int l = l0 + r0 + r;
            float sig;
            if (lane == 0) {
                float x  = SG[((size_t)b * NL + l) * NH + h];
                float sm = 1.0f / (1.0f + __expf(-5.0f * x));
                float yf = sm + 1e-5f;                       // matches ref fp32 add
                // 3^yf in double, round to fp32 (replicates XLA fp32 pow quantization),
                // then subtract 1 — avoids divergence from ref on cancellation-critical rows
                float p3 = (float)exp((double)yf * 1.0986122886681098);
                sig = p3 - 1.0f;
            }
            sig = __shfl_sync(0xffffffffu, sig, 0);
            const float amp     = c0 / sig;
            const float ninv2s2 = -1.0f / (2.0f * sig * sig);
            float* pp = out + V_SIZE + SER_SIZE + (((size_t)b * NH + h) * NL + l) * NS;
            #pragma unroll
            for (int j = 0; j < 4; j++) {
                int s = j * 128 + lane * 4;
                float d0 = (float)(l - s);
                float d1 = (float)(l - (s + 1));
                float d2 = (float)(l - (s + 2));
                float d3 = (float)(l - (s + 3));
                float4 o;
                o.x = amp * __expf(ninv2s2 * d0 * d0);
                o.y = amp * __expf(ninv2s2 * d1 * d1);
                o.z = amp * __expf(ninv2s2 * d2 * d2);
                o.w = amp * __expf(ninv2s2 * d3 * d3);
                *(float4*)&pp[s] = o;
            }
        }
    }

    // ---- V = P @ values ; lane owns d = {2*lane, 2*lane+1} for 4 rows ----
    float2 vacc[4];
    #pragma unroll
    for (int r = 0; r < 4; r++) vacc[r] = make_float2(0.f, 0.f);

    for (int c = 0; c < 4; c++) {
        __syncthreads();  // Ps fully written (incl. cross-lane) + protect Vs reuse
        {
            const int e  = tid & 63;
            const int ss = tid >> 6;
            const float* vc = vcol + (size_t)(c * 128) * (NH * NE);
            #pragma unroll
            for (int i = 0; i < 32; i++) {
                int s = ss + i * 4;
                Vs[s * 64 + e] = vc[(size_t)s * (NH * NE) + e];
            }
        }
        __syncthreads();
        #pragma unroll 16
        for (int s = 0; s < 128; s += 2) {
            float2 v0 = *(const float2*)&Vs[s * 64 + 2 * lane];
            float2 v1 = *(const float2*)&Vs[(s + 1) * 64 + 2 * lane];
            #pragma unroll
            for (int r = 0; r < 4; r++) {
                float2 pq = *(const float2*)&Ps[(r0 + r) * 512 + c * 128 + s];
                vacc[r] = ffma2(make_float2(pq.x, pq.x), v0, vacc[r]);
                vacc[r] = ffma2(make_float2(pq.y, pq.y), v1, vacc[r]);
            }
        }
    }

    #pragma unroll
    for (int r = 0; r < 4; r++) {
        float* vp = out + ((size_t)(b * NL + l0 + r0 + r) * NH + h) * NE;
        *(float2*)&vp[2 * lane] = vacc[r];
    }
}

extern "C" void kernel_launch(void* const* d_in, const int* in_sizes, int n_in,
                              void* d_out, int out_size) {
    (void)in_sizes; (void)n_in; (void)out_size;
    const float* q  = (const float*)d_in[0];
    const float* k  = (const float*)d_in[1];
    const float* v  = (const float*)d_in[2];
    const float* sg = (const float*)d_in[3];
    float* out = (float*)d_out;

    cudaFuncSetAttribute(anomaly_kernel,
                         cudaFuncAttributeMaxDynamicSharedMemorySize,
                         SMEM_FLOATS * (int)sizeof(float));

    dim3 grid(NB * NH * (NL / ROWS));  // 4096 blocks
    anomaly_kernel<<<grid, NTHREADS, SMEM_FLOATS * sizeof(float)>>>(q, k, v, sg, out);
}